// round 11
// baseline (speedup 1.0000x reference)
#include <cuda_runtime.h>
#include <cfloat>
#include <math.h>

// Fixed problem shape (setup_inputs): N=8192, IN_F=512, OUT_F=64, C=2, k=32
#define N_     8192
#define INF_   512
#define OUTF_  64
#define C_     2
#define WCAP   64      // per-warp candidate capacity (13 sigma)
#define CAP    512     // 8 * WCAP
#define KMAX   64
#define T0     2.2f

// Scratch for h = x @ W^T  [N_, OUTF_]  (2MB, device global: no allocations)
__device__ float g_h[N_ * OUTF_];

// ---------------------------------------------------------------------------
// Kernel 1: h = x @ W^T. Block = 32 rows x 64 f, 128 threads, 4x4 tile.
// Same scalar-LDS + stride-65 pattern as proven R8 kernel; grid=256 covers
// all 148 SMs with 2 CTAs/SM.
// ---------------------------------------------------------------------------
__global__ void __launch_bounds__(128) h_kernel(const float* __restrict__ x,
                                                const float* __restrict__ W) {
    __shared__ float x_s[32 * 64];   // [row][kk]    8KB
    __shared__ float w_s[64 * 65];   // [f][kk] pad 16.25KB
    const int t  = threadIdx.x;
    const int tx = t & 15;           // f lane: f = tx + 16*i
    const int ty = t >> 4;           // rows ty*4 .. ty*4+3 (ty 0..7)
    const int rowBase = blockIdx.x * 32;

    const float4* x4 = (const float4*)x;   // row = 128 float4
    const float4* W4 = (const float4*)W;

    float acc[4][4];
#pragma unroll
    for (int j = 0; j < 4; j++)
#pragma unroll
        for (int i = 0; i < 4; i++) acc[j][i] = 0.f;

    for (int ch = 0; ch < 8; ch++) {   // 64-kk chunks
#pragma unroll
        for (int i = 0; i < 4; i++) {  // x: 512 float4
            int idx = t + 128 * i;
            int rr = idx >> 4, c4 = idx & 15;
            float4 a = x4[(long)(rowBase + rr) * 128 + ch * 16 + c4];
            *(float4*)&x_s[rr * 64 + c4 * 4] = a;
        }
#pragma unroll
        for (int i = 0; i < 8; i++) {  // W: 1024 float4
            int idx = t + 128 * i;
            int ff = idx >> 4, c4 = idx & 15;
            float4 b = W4[(long)ff * 128 + ch * 16 + c4];
            float* d = &w_s[ff * 65 + c4 * 4];
            d[0] = b.x; d[1] = b.y; d[2] = b.z; d[3] = b.w;
        }
        __syncthreads();

#pragma unroll 4
        for (int kk = 0; kk < 64; kk++) {
            float xv[4], wv[4];
#pragma unroll
            for (int j = 0; j < 4; j++) xv[j] = x_s[(ty * 4 + j) * 64 + kk];
#pragma unroll
            for (int i = 0; i < 4; i++) wv[i] = w_s[(tx + 16 * i) * 65 + kk];
#pragma unroll
            for (int j = 0; j < 4; j++)
#pragma unroll
                for (int i = 0; i < 4; i++)
                    acc[j][i] = fmaf(xv[j], wv[i], acc[j][i]);
        }
        __syncthreads();
    }
#pragma unroll
    for (int j = 0; j < 4; j++)
#pragma unroll
        for (int i = 0; i < 4; i++)
            g_h[(long)(rowBase + ty * 4 + j) * OUTF_ + tx + 16 * i] = acc[j][i];
}

// ---------------------------------------------------------------------------
// Kernel 2 (fused): per attention row (16384 blocks, 256 threads).
// Stream: 4-batched ldcs + interleaved zero stcs; group-max filter gates the
// rare per-element extraction (packed u64 keys: exact jax order as one cmp).
// Rank: count keys greater. skey[0] is the row max (no reduction needed).
// ---------------------------------------------------------------------------
__global__ void __launch_bounds__(256) topk_kernel(const float* __restrict__ araw,
                                                   const int*   __restrict__ kptr,
                                                   float*       __restrict__ out,
                                                   float*       __restrict__ att) {
    __shared__ unsigned long long ckw[8][WCAP];   // per-warp key buffers
    __shared__ unsigned long long ckey[CAP];      // compacted keys
    __shared__ unsigned long long skey[KMAX];     // rank-ordered top keys
    __shared__ float sw[KMAX];
    __shared__ int   s_cw[8];
    __shared__ float s_bv[8];
    __shared__ int   s_bi[8];
    __shared__ float s_inv;
    __shared__ float s_lastV;
    __shared__ int   s_lastI;

    const int t    = threadIdx.x;
    const int lane = t & 31;
    const int wid  = t >> 5;
    const long r   = blockIdx.x;

    int k = 32;
    if (kptr) { k = *kptr; if (k < 1) k = 1; if (k > KMAX) k = KMAX; }

    if (t < 8) s_cw[t] = 0;
    __syncthreads();

    // ---- stream: 4-batched loads (MLP=4), interleaved zero stores ----
    const float4* src = (const float4*)(araw + r * (long)N_);
    float4* dst = att ? (float4*)(att + r * (long)N_) : nullptr;
    const float4 z = make_float4(0.f, 0.f, 0.f, 0.f);

#define EXTK(val, gi) do {                                                     \
        int p_ = atomicAdd(&s_cw[wid], 1);                                     \
        if (p_ < WCAP)                                                         \
            ckw[wid][p_] = ((unsigned long long)__float_as_uint(val) << 32)    \
                           | (unsigned)(N_ - 1 - (gi));                        \
    } while (0)

#pragma unroll
    for (int g = 0; g < 2; g++) {
        float4 v[4];
#pragma unroll
        for (int i = 0; i < 4; i++)
            v[i] = __ldcs(src + t + 256 * (g * 4 + i));     // 4 in flight
        if (dst) {
#pragma unroll
            for (int i = 0; i < 4; i++)
                __stcs(dst + t + 256 * (g * 4 + i), z);
        }
#pragma unroll
        for (int i = 0; i < 4; i++) {
            // group-max filter: per-element work only if any elem >= T0 (~5%)
            float gm = fmaxf(fmaxf(v[i].x, v[i].y), fmaxf(v[i].z, v[i].w));
            if (gm >= T0) {
                int b4 = 4 * (t + 256 * (g * 4 + i));
                if (v[i].x >= T0) EXTK(v[i].x, b4);
                if (v[i].y >= T0) EXTK(v[i].y, b4 + 1);
                if (v[i].z >= T0) EXTK(v[i].z, b4 + 2);
                if (v[i].w >= T0) EXTK(v[i].w, b4 + 3);
            }
        }
    }
#undef EXTK
    __syncthreads();

    // ---- merge per-warp counts ----
    int cnts[8], offs[8], m = 0;
    bool ok = true;
#pragma unroll
    for (int j = 0; j < 8; j++) {
        cnts[j] = s_cw[j];
        offs[j] = m;
        m += cnts[j];
        ok = ok && (cnts[j] <= WCAP);
    }
    ok = ok && (m >= k);

    if (ok) {
        // compact per-warp key lists
#pragma unroll
        for (int j = 0; j < 8; j++)
            for (int i = t; i < cnts[j]; i += 256)
                ckey[offs[j] + i] = ckw[j][i];
        __syncthreads();

        // exact rank: one u64 compare encodes (value desc, index asc)
        for (int i = t; i < m; i += 256) {
            unsigned long long key = ckey[i];
            int rank = 0;
            for (int j = 0; j < m; j++) rank += (ckey[j] > key);
            if (rank < k) skey[rank] = key;
        }
        __syncthreads();
    } else {
        // robust fallback: k deterministic arg-max passes over the global row
        if (t == 0) { s_lastV = FLT_MAX; s_lastI = -1; }
        __syncthreads();
        const float* rowg = araw + r * (long)N_;
        for (int p = 0; p < k; p++) {
            float lastV = s_lastV; int lastI = s_lastI;
            float bv = -FLT_MAX; int bi = N_;
            for (int e = t; e < N_; e += 256) {
                float vv = rowg[e];
                bool after = (vv < lastV) || (vv == lastV && e > lastI);
                if (after && ((vv > bv) || (vv == bv && e < bi))) { bv = vv; bi = e; }
            }
#pragma unroll
            for (int o = 16; o > 0; o >>= 1) {
                float ov = __shfl_xor_sync(0xffffffffu, bv, o);
                int   oi = __shfl_xor_sync(0xffffffffu, bv == ov ? bi : bi, o);
                oi = __shfl_xor_sync(0xffffffffu, bi, o);
                if ((ov > bv) || (ov == bv && oi < bi)) { bv = ov; bi = oi; }
            }
            if (lane == 0) { s_bv[wid] = bv; s_bi[wid] = bi; }
            __syncthreads();
            if (t == 0) {
                float gv = s_bv[0]; int gi = s_bi[0];
#pragma unroll
                for (int j = 1; j < 8; j++) {
                    if ((s_bv[j] > gv) || (s_bv[j] == gv && s_bi[j] < gi)) { gv = s_bv[j]; gi = s_bi[j]; }
                }
                skey[p] = ((unsigned long long)__float_as_uint(gv) << 32)
                          | (unsigned)(N_ - 1 - gi);
                s_lastV = gv; s_lastI = gi;
            }
            __syncthreads();
        }
    }

    // ---- softmax weights: M = value of skey[0] (the exact row max) ----
    if (t < KMAX) {
        float sv = 0.f;
        if (t < k) {
            float M = __uint_as_float((unsigned)(skey[0] >> 32));
            float v = __uint_as_float((unsigned)(skey[t] >> 32));
            sv = expf(v - M);
        }
        sw[t] = sv;
    }
    __syncthreads();

    // deterministic denominator: fixed warp-0 shuffle tree
    if (wid == 0) {
        float s = sw[lane] + sw[lane + 32];
#pragma unroll
        for (int o = 16; o > 0; o >>= 1)
            s += __shfl_xor_sync(0xffffffffu, s, o);
        if (lane == 0) s_inv = 1.0f / s;
    }
    __syncthreads();
    if (t < k) sw[t] *= s_inv;   // premultiply
    __syncthreads();

    // ---- scatter the k softmax values (zeros already streamed out) ----
    if (att && t < k) {
        int idx = N_ - 1 - (int)(skey[t] & 0xffffffffu);
        att[r * (long)N_ + idx] = sw[t];
    }

    // ---- h_prime row -> concat-transposed output [n, c*OUTF + f] ----
    if (out && t < OUTF_) {
        float acc = 0.f;
        for (int p = 0; p < k; p++) {
            int idx = N_ - 1 - (int)(skey[p] & 0xffffffffu);
            acc = fmaf(sw[p], g_h[(long)idx * OUTF_ + t], acc);
        }
        const int c = (int)(r / N_);
        const int n = (int)(r % N_);
        out[(long)n * (C_ * OUTF_) + c * OUTF_ + t] = acc;
    }
}

// ---------------------------------------------------------------------------
extern "C" void kernel_launch(void* const* d_in, const int* in_sizes, int n_in,
                              void* d_out, int out_size) {
    const float* x    = (const float*)d_in[0];
    const float* W    = (const float*)d_in[1];
    const float* araw = (const float*)d_in[2];
    const int*   kptr = (n_in > 3) ? (const int*)d_in[3] : nullptr;

    const long attElems = (long)in_sizes[2];        // R * N
    const int  R        = (int)(attElems / N_);     // 16384
    const long outElems = (long)N_ * C_ * OUTF_;    // 1,048,576

    float* outp = nullptr;
    float* attp = nullptr;
    const long osz = (long)out_size;
    if (osz >= outElems + attElems) {
        outp = (float*)d_out;
        attp = (float*)d_out + outElems;   // tuple order: (out, att)
    } else if (osz == attElems) {
        attp = (float*)d_out;
    } else {
        outp = (float*)d_out;
    }

    if (outp) h_kernel<<<N_ / 32, 128>>>(x, W);
    topk_kernel<<<R, 256>>>(araw, kptr, outp, attp);
}

// round 13
// speedup vs baseline: 1.1200x; 1.1200x over previous
#include <cuda_runtime.h>
#include <cstdint>
#include <cfloat>
#include <math.h>

// Fixed problem shape (setup_inputs): N=8192, IN_F=512, OUT_F=64, C=2, k=32
#define N_     8192
#define INF_   512
#define OUTF_  64
#define C_     2
#define WCAP   64      // per-warp candidate capacity (13 sigma)
#define CAP    512     // 8 * WCAP
#define KMAX   64
#define T0     2.2f

// Scratch for h = x @ W^T  [N_, OUTF_]  (2MB, device global: no allocations)
__device__ float g_h[N_ * OUTF_];

// ---------------------------------------------------------------------------
// Kernel 1: h = x @ W^T. Proven R8/R10 version (33us): block = 64 rows x 64 f,
// 256 threads, 4x4 tile, W smem stride-65 -> conflict-free scalar LDS.
// ---------------------------------------------------------------------------
__global__ void __launch_bounds__(256) h_kernel(const float* __restrict__ x,
                                                const float* __restrict__ W) {
    __shared__ float x_s[64 * 64];   // [row][kk]   16KB
    __shared__ float w_s[64 * 65];   // [f][kk] pad 16.25KB
    const int t  = threadIdx.x;
    const int tx = t & 15;           // f lane: f = tx + 16*i
    const int ty = t >> 4;           // rows ty*4 .. ty*4+3
    const int rowBase = blockIdx.x * 64;

    const float4* x4 = (const float4*)x;   // row = 128 float4
    const float4* W4 = (const float4*)W;

    float acc[4][4];
#pragma unroll
    for (int j = 0; j < 4; j++)
#pragma unroll
        for (int i = 0; i < 4; i++) acc[j][i] = 0.f;

    for (int ch = 0; ch < 8; ch++) {   // 64-kk chunks
#pragma unroll
        for (int i = 0; i < 4; i++) {
            int idx = t + 256 * i;         // 0..1023
            int rr = idx >> 4, c4 = idx & 15;
            float4 a = x4[(long)(rowBase + rr) * 128 + ch * 16 + c4];
            *(float4*)&x_s[rr * 64 + c4 * 4] = a;
            float4 b = W4[(long)rr * 128 + ch * 16 + c4];  // rr = f here
            float* d = &w_s[rr * 65 + c4 * 4];
            d[0] = b.x; d[1] = b.y; d[2] = b.z; d[3] = b.w;
        }
        __syncthreads();

#pragma unroll 4
        for (int kk = 0; kk < 64; kk++) {
            float xv[4], wv[4];
#pragma unroll
            for (int j = 0; j < 4; j++) xv[j] = x_s[(ty * 4 + j) * 64 + kk];
#pragma unroll
            for (int i = 0; i < 4; i++) wv[i] = w_s[(tx + 16 * i) * 65 + kk];
#pragma unroll
            for (int j = 0; j < 4; j++)
#pragma unroll
                for (int i = 0; i < 4; i++)
                    acc[j][i] = fmaf(xv[j], wv[i], acc[j][i]);
        }
        __syncthreads();
    }
#pragma unroll
    for (int j = 0; j < 4; j++)
#pragma unroll
        for (int i = 0; i < 4; i++)
            g_h[(long)(rowBase + ty * 4 + j) * OUTF_ + tx + 16 * i] = acc[j][i];
}

// ---------------------------------------------------------------------------
// Kernel 2 (fused): per attention row (16384 blocks, 256 threads).
// Zero-fill of the att row is offloaded to cp.async.bulk (smem zero buffer ->
// global, 8 x 4KB, issued once by thread 0) so the hot loop issues ONLY loads
// + extraction. wait_group 0 + barrier orders zeros before the k-scatter.
// Rank/softmax identical to proven R10.
// ---------------------------------------------------------------------------
__global__ void __launch_bounds__(256) topk_kernel(const float* __restrict__ araw,
                                                   const int*   __restrict__ kptr,
                                                   float*       __restrict__ out,
                                                   float*       __restrict__ att) {
    __shared__ float4 z_s[256];      // 4KB of zeros (bulk-copy source)
    __shared__ float cvw[8][WCAP];
    __shared__ int   ciw[8][WCAP];
    __shared__ int   s_cw[8];
    __shared__ float cval[CAP];
    __shared__ int   cidx[CAP];
    __shared__ int   sidx[KMAX];
    __shared__ float sw[KMAX];
    __shared__ float s_red[8];
    __shared__ float s_bv[8];
    __shared__ int   s_bi[8];
    __shared__ float s_M;
    __shared__ float s_inv;
    __shared__ float s_lastV;
    __shared__ int   s_lastI;

    const int t    = threadIdx.x;
    const int lane = t & 31;
    const int wid  = t >> 5;
    const long r   = blockIdx.x;

    int k = 32;
    if (kptr) { k = *kptr; if (k < 1) k = 1; if (k > KMAX) k = KMAX; }

    z_s[t] = make_float4(0.f, 0.f, 0.f, 0.f);
    if (t < 8)    s_cw[t] = 0;
    if (t < KMAX) sw[t]   = 0.f;   // zero-pad for fixed-tree sum
    __syncthreads();

    // ---- offload att-row zero-fill to the async bulk engine ----
    if (att && t == 0) {
        asm volatile("fence.proxy.async;" ::: "memory");
        unsigned int saddr;
        asm("{ .reg .u64 tmp; cvta.to.shared.u64 tmp, %1; cvt.u32.u64 %0, tmp; }"
            : "=r"(saddr) : "l"((const void*)z_s));
        char* gdst = (char*)(att + r * (long)N_);
#pragma unroll
        for (int i = 0; i < 8; i++) {
            asm volatile(
                "cp.async.bulk.global.shared::cta.bulk_group [%0], [%1], %2;"
                :: "l"(gdst + i * 4096), "r"(saddr), "r"(4096) : "memory");
        }
        asm volatile("cp.async.bulk.commit_group;" ::: "memory");
    }

    // ---- stream: 4-batched loads (MLP=4), extraction only (NO stores) ----
    const float4* src = (const float4*)(araw + r * (long)N_);

#define EXT(val, gi) do {                                                      \
        if ((val) >= T0) {                                                     \
            int p_ = atomicAdd(&s_cw[wid], 1);                                 \
            if (p_ < WCAP) { cvw[wid][p_] = (val); ciw[wid][p_] = (gi); }      \
        }                                                                      \
    } while (0)

#pragma unroll
    for (int g = 0; g < 2; g++) {
        float4 v[4];
#pragma unroll
        for (int i = 0; i < 4; i++)
            v[i] = __ldcs(src + t + 256 * (g * 4 + i));     // 4 in flight
#pragma unroll
        for (int i = 0; i < 4; i++) {
            int b4 = 4 * (t + 256 * (g * 4 + i));
            EXT(v[i].x, b4);
            EXT(v[i].y, b4 + 1);
            EXT(v[i].z, b4 + 2);
            EXT(v[i].w, b4 + 3);
        }
    }
#undef EXT
    __syncthreads();

    // ---- merge per-warp counts ----
    int cnts[8], offs[8], m = 0;
    bool ok = true;
#pragma unroll
    for (int j = 0; j < 8; j++) {
        cnts[j] = s_cw[j];
        offs[j] = m;
        m += cnts[j];
        ok = ok && (cnts[j] <= WCAP);
    }
    ok = ok && (m >= k);

    if (ok) {
        // compact per-warp lists into contiguous cval/cidx
#pragma unroll
        for (int j = 0; j < 8; j++)
            for (int i = t; i < cnts[j]; i += 256) {
                cval[offs[j] + i] = cvw[j][i];
                cidx[offs[j] + i] = ciw[j][i];
            }
        __syncthreads();

        // max over candidates (row max is among them since m >= k >= 1)
        float lm = -FLT_MAX;
        for (int i = t; i < m; i += 256) lm = fmaxf(lm, cval[i]);
#pragma unroll
        for (int o = 16; o > 0; o >>= 1)
            lm = fmaxf(lm, __shfl_xor_sync(0xffffffffu, lm, o));
        if (lane == 0) s_red[wid] = lm;
        __syncthreads();
        if (t == 0) {
            float mm = s_red[0];
#pragma unroll
            for (int j = 1; j < 8; j++) mm = fmaxf(mm, s_red[j]);
            s_M = mm;
        }
        __syncthreads();
        const float M = s_M;

        // exact rank: value desc, index asc (jax tie-break)
        for (int i = t; i < m; i += 256) {
            float vi = cval[i];
            int   ii = cidx[i];
            int rank = 0;
            for (int j = 0; j < m; j++) {
                float vj = cval[j];
                rank += (vj > vi) || (vj == vi && cidx[j] < ii);
            }
            if (rank < k) { sidx[rank] = ii; sw[rank] = expf(vi - M); }
        }
        __syncthreads();
    } else {
        // robust fallback: k deterministic arg-max passes over the global row
        if (t == 0) { s_lastV = FLT_MAX; s_lastI = -1; }
        __syncthreads();
        const float* rowg = araw + r * (long)N_;
        for (int p = 0; p < k; p++) {
            float lastV = s_lastV; int lastI = s_lastI;
            float bv = -FLT_MAX; int bi = N_;
            for (int e = t; e < N_; e += 256) {
                float vv = rowg[e];
                bool after = (vv < lastV) || (vv == lastV && e > lastI);
                if (after && ((vv > bv) || (vv == bv && e < bi))) { bv = vv; bi = e; }
            }
#pragma unroll
            for (int o = 16; o > 0; o >>= 1) {
                float ov = __shfl_xor_sync(0xffffffffu, bv, o);
                int   oi = __shfl_xor_sync(0xffffffffu, bi, o);
                if ((ov > bv) || (ov == bv && oi < bi)) { bv = ov; bi = oi; }
            }
            if (lane == 0) { s_bv[wid] = bv; s_bi[wid] = bi; }
            __syncthreads();
            if (t == 0) {
                float gv = s_bv[0]; int gi = s_bi[0];
#pragma unroll
                for (int j = 1; j < 8; j++) {
                    if ((s_bv[j] > gv) || (s_bv[j] == gv && s_bi[j] < gi)) { gv = s_bv[j]; gi = s_bi[j]; }
                }
                if (p == 0) s_M = gv;
                sidx[p] = gi; sw[p] = expf(gv - s_M);
                s_lastV = gv; s_lastI = gi;
            }
            __syncthreads();
        }
    }

    // ---- deterministic softmax denominator: fixed warp-0 shuffle tree ----
    if (wid == 0) {
        float s = sw[lane] + sw[lane + 32];
#pragma unroll
        for (int o = 16; o > 0; o >>= 1)
            s += __shfl_xor_sync(0xffffffffu, s, o);
        if (lane == 0) s_inv = 1.0f / s;
    }

    // ---- bulk zeros must land before the scatter ----
    if (att && t == 0)
        asm volatile("cp.async.bulk.wait_group 0;" ::: "memory");
    __syncthreads();
    const float inv = s_inv;

    // ---- scatter the k softmax values over the zeroed row ----
    if (att && t < k) att[r * (long)N_ + sidx[t]] = sw[t] * inv;

    // ---- h_prime row -> concat-transposed output [n, c*OUTF + f] ----
    if (out && t < OUTF_) {
        float acc = 0.f;
        for (int p = 0; p < k; p++)
            acc = fmaf(sw[p] * inv, g_h[(long)sidx[p] * OUTF_ + t], acc);
        const int c = (int)(r / N_);
        const int n = (int)(r % N_);
        out[(long)n * (C_ * OUTF_) + c * OUTF_ + t] = acc;
    }
}

// ---------------------------------------------------------------------------
extern "C" void kernel_launch(void* const* d_in, const int* in_sizes, int n_in,
                              void* d_out, int out_size) {
    const float* x    = (const float*)d_in[0];
    const float* W    = (const float*)d_in[1];
    const float* araw = (const float*)d_in[2];
    const int*   kptr = (n_in > 3) ? (const int*)d_in[3] : nullptr;

    const long attElems = (long)in_sizes[2];        // R * N
    const int  R        = (int)(attElems / N_);     // 16384
    const long outElems = (long)N_ * C_ * OUTF_;    // 1,048,576

    float* outp = nullptr;
    float* attp = nullptr;
    const long osz = (long)out_size;
    if (osz >= outElems + attElems) {
        outp = (float*)d_out;
        attp = (float*)d_out + outElems;   // tuple order: (out, att)
    } else if (osz == attElems) {
        attp = (float*)d_out;
    } else {
        outp = (float*)d_out;
    }

    if (outp) h_kernel<<<N_ / 64, 256>>>(x, W);
    topk_kernel<<<R, 256>>>(araw, kptr, outp, attp);
}

// round 14
// speedup vs baseline: 1.1506x; 1.0273x over previous
#include <cuda_runtime.h>
#include <cstdint>
#include <cfloat>
#include <math.h>

// Fixed problem shape (setup_inputs): N=8192, IN_F=512, OUT_F=64, C=2, k=32
#define N_     8192
#define INF_   512
#define OUTF_  64
#define C_     2
#define WCAP   64      // per-warp candidate capacity (13 sigma)
#define CAP    512     // 8 * WCAP
#define KMAX   64
#define T0     2.2f

// Scratch for h = x @ W^T  [N_, OUTF_]  (2MB, device global: no allocations)
__device__ float g_h[N_ * OUTF_];

// ---------------------------------------------------------------------------
// Kernel 1: h = x @ W^T. Block = 64 rows x 64 f, 256 threads, 4x4 tile.
// float4 LDS both operands, stride 17 float4 (68 floats) padding:
//   w: lanes tx*17 mod 32 all distinct (16 addrs, upper half-warp broadcasts)
//   x: rows j vs j+4 -> 17j vs 17j+4 mod 32, distinct
// Per kk-quad: 8 LDS.128 per 64 FMA -> FMA-bound.
// ---------------------------------------------------------------------------
__global__ void __launch_bounds__(256) h_kernel(const float* __restrict__ x,
                                                const float* __restrict__ W) {
    __shared__ float4 x_s[64 * 17];   // [row][kk4] pad   17.4KB
    __shared__ float4 w_s[64 * 17];   // [f][kk4] pad     17.4KB
    const int t  = threadIdx.x;
    const int tx = t & 15;            // f lane: f = tx + 16*i
    const int ty = t >> 4;            // rows ty*4 .. ty*4+3
    const int rowBase = blockIdx.x * 64;

    const float4* x4 = (const float4*)x;   // row = 128 float4
    const float4* W4 = (const float4*)W;

    float acc[4][4];
#pragma unroll
    for (int j = 0; j < 4; j++)
#pragma unroll
        for (int i = 0; i < 4; i++) acc[j][i] = 0.f;

    for (int ch = 0; ch < 8; ch++) {   // 64-kk chunks (16 float4 each)
#pragma unroll
        for (int i = 0; i < 4; i++) {
            int idx = t + 256 * i;          // 0..1023
            int rr = idx >> 4, c4 = idx & 15;
            x_s[rr * 17 + c4] = x4[(long)(rowBase + rr) * 128 + ch * 16 + c4];
            w_s[rr * 17 + c4] = W4[(long)rr * 128 + ch * 16 + c4];  // rr = f
        }
        __syncthreads();

#pragma unroll 4
        for (int q = 0; q < 16; q++) {   // kk4 within chunk
            float4 xq[4], wq[4];
#pragma unroll
            for (int j = 0; j < 4; j++) xq[j] = x_s[(ty * 4 + j) * 17 + q];
#pragma unroll
            for (int i = 0; i < 4; i++) wq[i] = w_s[(tx + 16 * i) * 17 + q];
#pragma unroll
            for (int j = 0; j < 4; j++)
#pragma unroll
                for (int i = 0; i < 4; i++) {
                    acc[j][i] = fmaf(xq[j].x, wq[i].x, acc[j][i]);
                    acc[j][i] = fmaf(xq[j].y, wq[i].y, acc[j][i]);
                    acc[j][i] = fmaf(xq[j].z, wq[i].z, acc[j][i]);
                    acc[j][i] = fmaf(xq[j].w, wq[i].w, acc[j][i]);
                }
        }
        __syncthreads();
    }
#pragma unroll
    for (int j = 0; j < 4; j++)
#pragma unroll
        for (int i = 0; i < 4; i++)
            g_h[(long)(rowBase + ty * 4 + j) * OUTF_ + tx + 16 * i] = acc[j][i];
}

// ---------------------------------------------------------------------------
// Kernel 2 (fused): per attention row (16384 blocks, 256 threads).
// Zero-fill offloaded to cp.async.bulk (proven R13). NEW: group-max filter —
// per-element extraction only runs in the ~5% of float4 groups whose max
// clears T0. Rank/softmax identical to proven R10/R13.
// ---------------------------------------------------------------------------
__global__ void __launch_bounds__(256) topk_kernel(const float* __restrict__ araw,
                                                   const int*   __restrict__ kptr,
                                                   float*       __restrict__ out,
                                                   float*       __restrict__ att) {
    __shared__ float4 z_s[256];      // 4KB of zeros (bulk-copy source)
    __shared__ float cvw[8][WCAP];
    __shared__ int   ciw[8][WCAP];
    __shared__ int   s_cw[8];
    __shared__ float cval[CAP];
    __shared__ int   cidx[CAP];
    __shared__ int   sidx[KMAX];
    __shared__ float sw[KMAX];
    __shared__ float s_red[8];
    __shared__ float s_bv[8];
    __shared__ int   s_bi[8];
    __shared__ float s_M;
    __shared__ float s_inv;
    __shared__ float s_lastV;
    __shared__ int   s_lastI;

    const int t    = threadIdx.x;
    const int lane = t & 31;
    const int wid  = t >> 5;
    const long r   = blockIdx.x;

    int k = 32;
    if (kptr) { k = *kptr; if (k < 1) k = 1; if (k > KMAX) k = KMAX; }

    z_s[t] = make_float4(0.f, 0.f, 0.f, 0.f);
    if (t < 8)    s_cw[t] = 0;
    if (t < KMAX) sw[t]   = 0.f;   // zero-pad for fixed-tree sum
    __syncthreads();

    // ---- offload att-row zero-fill to the async bulk engine ----
    if (att && t == 0) {
        asm volatile("fence.proxy.async;" ::: "memory");
        unsigned int saddr;
        asm("{ .reg .u64 tmp; cvta.to.shared.u64 tmp, %1; cvt.u32.u64 %0, tmp; }"
            : "=r"(saddr) : "l"((const void*)z_s));
        char* gdst = (char*)(att + r * (long)N_);
#pragma unroll
        for (int i = 0; i < 8; i++) {
            asm volatile(
                "cp.async.bulk.global.shared::cta.bulk_group [%0], [%1], %2;"
                :: "l"(gdst + i * 4096), "r"(saddr), "r"(4096) : "memory");
        }
        asm volatile("cp.async.bulk.commit_group;" ::: "memory");
    }

    // ---- stream: 4-batched loads (MLP=4), group-max-gated extraction ----
    const float4* src = (const float4*)(araw + r * (long)N_);

#define EXT(val, gi) do {                                                      \
        if ((val) >= T0) {                                                     \
            int p_ = atomicAdd(&s_cw[wid], 1);                                 \
            if (p_ < WCAP) { cvw[wid][p_] = (val); ciw[wid][p_] = (gi); }      \
        }                                                                      \
    } while (0)

#pragma unroll
    for (int g = 0; g < 2; g++) {
        float4 v[4];
#pragma unroll
        for (int i = 0; i < 4; i++)
            v[i] = __ldcs(src + t + 256 * (g * 4 + i));     // 4 in flight
#pragma unroll
        for (int i = 0; i < 4; i++) {
            float gm = fmaxf(fmaxf(v[i].x, v[i].y), fmaxf(v[i].z, v[i].w));
            if (gm >= T0) {   // ~5.4% of groups
                int b4 = 4 * (t + 256 * (g * 4 + i));
                EXT(v[i].x, b4);
                EXT(v[i].y, b4 + 1);
                EXT(v[i].z, b4 + 2);
                EXT(v[i].w, b4 + 3);
            }
        }
    }
#undef EXT
    __syncthreads();

    // ---- merge per-warp counts ----
    int cnts[8], offs[8], m = 0;
    bool ok = true;
#pragma unroll
    for (int j = 0; j < 8; j++) {
        cnts[j] = s_cw[j];
        offs[j] = m;
        m += cnts[j];
        ok = ok && (cnts[j] <= WCAP);
    }
    ok = ok && (m >= k);

    if (ok) {
        // compact per-warp lists into contiguous cval/cidx
#pragma unroll
        for (int j = 0; j < 8; j++)
            for (int i = t; i < cnts[j]; i += 256) {
                cval[offs[j] + i] = cvw[j][i];
                cidx[offs[j] + i] = ciw[j][i];
            }
        __syncthreads();

        // max over candidates (row max is among them since m >= k >= 1)
        float lm = -FLT_MAX;
        for (int i = t; i < m; i += 256) lm = fmaxf(lm, cval[i]);
#pragma unroll
        for (int o = 16; o > 0; o >>= 1)
            lm = fmaxf(lm, __shfl_xor_sync(0xffffffffu, lm, o));
        if (lane == 0) s_red[wid] = lm;
        __syncthreads();
        if (t == 0) {
            float mm = s_red[0];
#pragma unroll
            for (int j = 1; j < 8; j++) mm = fmaxf(mm, s_red[j]);
            s_M = mm;
        }
        __syncthreads();
        const float M = s_M;

        // exact rank: value desc, index asc (jax tie-break)
        for (int i = t; i < m; i += 256) {
            float vi = cval[i];
            int   ii = cidx[i];
            int rank = 0;
            for (int j = 0; j < m; j++) {
                float vj = cval[j];
                rank += (vj > vi) || (vj == vi && cidx[j] < ii);
            }
            if (rank < k) { sidx[rank] = ii; sw[rank] = expf(vi - M); }
        }
        __syncthreads();
    } else {
        // robust fallback: k deterministic arg-max passes over the global row
        if (t == 0) { s_lastV = FLT_MAX; s_lastI = -1; }
        __syncthreads();
        const float* rowg = araw + r * (long)N_;
        for (int p = 0; p < k; p++) {
            float lastV = s_lastV; int lastI = s_lastI;
            float bv = -FLT_MAX; int bi = N_;
            for (int e = t; e < N_; e += 256) {
                float vv = rowg[e];
                bool after = (vv < lastV) || (vv == lastV && e > lastI);
                if (after && ((vv > bv) || (vv == bv && e < bi))) { bv = vv; bi = e; }
            }
#pragma unroll
            for (int o = 16; o > 0; o >>= 1) {
                float ov = __shfl_xor_sync(0xffffffffu, bv, o);
                int   oi = __shfl_xor_sync(0xffffffffu, bi, o);
                if ((ov > bv) || (ov == bv && oi < bi)) { bv = ov; bi = oi; }
            }
            if (lane == 0) { s_bv[wid] = bv; s_bi[wid] = bi; }
            __syncthreads();
            if (t == 0) {
                float gv = s_bv[0]; int gi = s_bi[0];
#pragma unroll
                for (int j = 1; j < 8; j++) {
                    if ((s_bv[j] > gv) || (s_bv[j] == gv && s_bi[j] < gi)) { gv = s_bv[j]; gi = s_bi[j]; }
                }
                if (p == 0) s_M = gv;
                sidx[p] = gi; sw[p] = expf(gv - s_M);
                s_lastV = gv; s_lastI = gi;
            }
            __syncthreads();
        }
    }

    // ---- deterministic softmax denominator: fixed warp-0 shuffle tree ----
    if (wid == 0) {
        float s = sw[lane] + sw[lane + 32];
#pragma unroll
        for (int o = 16; o > 0; o >>= 1)
            s += __shfl_xor_sync(0xffffffffu, s, o);
        if (lane == 0) s_inv = 1.0f / s;
    }

    // ---- bulk zeros must land before the scatter ----
    if (att && t == 0)
        asm volatile("cp.async.bulk.wait_group 0;" ::: "memory");
    __syncthreads();
    const float inv = s_inv;

    // ---- scatter the k softmax values over the zeroed row ----
    if (att && t < k) att[r * (long)N_ + sidx[t]] = sw[t] * inv;

    // ---- h_prime row -> concat-transposed output [n, c*OUTF + f] ----
    if (out && t < OUTF_) {
        float acc = 0.f;
        for (int p = 0; p < k; p++)
            acc = fmaf(sw[p] * inv, g_h[(long)sidx[p] * OUTF_ + t], acc);
        const int c = (int)(r / N_);
        const int n = (int)(r % N_);
        out[(long)n * (C_ * OUTF_) + c * OUTF_ + t] = acc;
    }
}

// ---------------------------------------------------------------------------
extern "C" void kernel_launch(void* const* d_in, const int* in_sizes, int n_in,
                              void* d_out, int out_size) {
    const float* x    = (const float*)d_in[0];
    const float* W    = (const float*)d_in[1];
    const float* araw = (const float*)d_in[2];
    const int*   kptr = (n_in > 3) ? (const int*)d_in[3] : nullptr;

    const long attElems = (long)in_sizes[2];        // R * N
    const int  R        = (int)(attElems / N_);     // 16384
    const long outElems = (long)N_ * C_ * OUTF_;    // 1,048,576

    float* outp = nullptr;
    float* attp = nullptr;
    const long osz = (long)out_size;
    if (osz >= outElems + attElems) {
        outp = (float*)d_out;
        attp = (float*)d_out + outElems;   // tuple order: (out, att)
    } else if (osz == attElems) {
        attp = (float*)d_out;
    } else {
        outp = (float*)d_out;
    }

    if (outp) h_kernel<<<N_ / 64, 256>>>(x, W);
    topk_kernel<<<R, 256>>>(araw, kptr, outp, attp);
}